// round 1
// baseline (speedup 1.0000x reference)
#include <cuda_runtime.h>
#include <math.h>

// Problem constants
#define B_   256
#define T_   36
#define S_   96
#define D_   1024
#define H_   1024
#define L_   2
#define KCAT 2048          // D_ + H_
#define G3   (3 * H_)      // 3072

// Output buffer layout (flattened tuple: output, hidden_f, attn_weights)
#define OUT_Y   ((size_t)0)
#define OUT_H   ((size_t)B_ * T_ * D_)                    // 9437184
#define OUT_AW  (OUT_H + (size_t)L_ * B_ * H_)            // 9961472

// Scratch (static __device__ — no allocations allowed)
__device__ float g_cat2[B_ * KCAT];   // [x | w_enc]
__device__ float g_xc[B_ * D_];       // relu(combine)
__device__ float g_gi[B_ * G3];       // input gates
__device__ float g_gh[B_ * G3];       // hidden gates
__device__ float g_y[B_ * D_];        // out1 result

// ---------------------------------------------------------------------------
// Fused attention logits + softmax.
// One block per batch row b. 8 warps; warp w handles s = w, w+8, ...
// cat1 = [target[b,t,:], hidden[L-1,b,:]] handled inline (1024 split boundary
// aligns with the 128-element warp chunks).
// Writes softmax result directly into the attn_weights output region.
// ---------------------------------------------------------------------------
__global__ void attn_softmax_kernel(const float* __restrict__ target,
                                    const float* __restrict__ hstate, // (L,B,H) region in d_out
                                    const float* __restrict__ W,      // (S, 2048)
                                    const float* __restrict__ bias,   // (S)
                                    float* __restrict__ aw_out,       // (B,T,S) region in d_out
                                    int t)
{
    const int b = blockIdx.x;
    const int tid = threadIdx.x;
    const int lane = tid & 31;
    const int w = tid >> 5;

    __shared__ float logits[S_];
    __shared__ float smax, ssum;

    const float* x = target + ((size_t)b * T_ + t) * D_;
    const float* h = hstate + ((size_t)(L_ - 1) * B_ + b) * H_;

    for (int s = w; s < S_; s += 8) {
        const float* wr = W + (size_t)s * KCAT;
        float acc = 0.f;
#pragma unroll
        for (int c = 0; c < 8; c++) {
            int k = c * 128 + lane * 4;
            float4 xv = *(const float4*)(x + k);
            float4 wv = *(const float4*)(wr + k);
            acc = fmaf(xv.x, wv.x, acc); acc = fmaf(xv.y, wv.y, acc);
            acc = fmaf(xv.z, wv.z, acc); acc = fmaf(xv.w, wv.w, acc);
        }
#pragma unroll
        for (int c = 0; c < 8; c++) {
            int k = c * 128 + lane * 4;
            float4 hv = *(const float4*)(h + k);
            float4 wv = *(const float4*)(wr + 1024 + k);
            acc = fmaf(hv.x, wv.x, acc); acc = fmaf(hv.y, wv.y, acc);
            acc = fmaf(hv.z, wv.z, acc); acc = fmaf(hv.w, wv.w, acc);
        }
#pragma unroll
        for (int o = 16; o > 0; o >>= 1)
            acc += __shfl_xor_sync(0xFFFFFFFFu, acc, o);
        if (lane == 0) logits[s] = acc + bias[s];
    }
    __syncthreads();

    if (w == 0) {
        float m = -1e30f;
        for (int s = lane; s < S_; s += 32) m = fmaxf(m, logits[s]);
#pragma unroll
        for (int o = 16; o > 0; o >>= 1)
            m = fmaxf(m, __shfl_xor_sync(0xFFFFFFFFu, m, o));
        if (lane == 0) smax = m;
    }
    __syncthreads();
    if (tid < S_) logits[tid] = expf(logits[tid] - smax);
    __syncthreads();
    if (w == 0) {
        float s0 = 0.f;
        for (int s = lane; s < S_; s += 32) s0 += logits[s];
#pragma unroll
        for (int o = 16; o > 0; o >>= 1)
            s0 += __shfl_xor_sync(0xFFFFFFFFu, s0, o);
        if (lane == 0) ssum = s0;
    }
    __syncthreads();
    if (tid < S_)
        aw_out[((size_t)b * T_ + t) * S_ + tid] = logits[tid] / ssum;
}

// ---------------------------------------------------------------------------
// w_enc[b,h] = sum_s aw[b,t,s] * enc[b,s,h], fused with building
// cat2 = [target[b,t,:], w_enc[b,:]]  (exploits D_ == H_ == 1024).
// Grid: (H_/256, B_), 256 threads.
// ---------------------------------------------------------------------------
__global__ void wenc_cat_kernel(const float* __restrict__ target,
                                const float* __restrict__ enc,   // (B,S,H)
                                const float* __restrict__ aw,    // (B,T,S) in d_out
                                float* __restrict__ cat2,
                                int t)
{
    const int b = blockIdx.y;
    const int h = blockIdx.x * 256 + threadIdx.x;

    __shared__ float a[S_];
    if (threadIdx.x < S_)
        a[threadIdx.x] = aw[((size_t)b * T_ + t) * S_ + threadIdx.x];
    __syncthreads();

    const float* e = enc + (size_t)b * S_ * H_ + h;
    float acc = 0.f;
#pragma unroll 8
    for (int s = 0; s < S_; s++)
        acc = fmaf(a[s], e[(size_t)s * H_], acc);

    cat2[(size_t)b * KCAT + h]        = target[((size_t)b * T_ + t) * D_ + h];
    cat2[(size_t)b * KCAT + 1024 + h] = acc;
}

// ---------------------------------------------------------------------------
// Generic fp32 GEMM:  C(M,N) = A(M,K) @ W(N,K)^T + bias, optional ReLU.
// Block tile 64x64, 256 threads, 4x4 per-thread tile, K-chunk 16.
// Requires M%64==0, N%64==0, K%16==0 (all shapes here comply).
// ---------------------------------------------------------------------------
__global__ void gemm_nt_kernel(const float* __restrict__ A, int lda,
                               const float* __restrict__ W, int ldw,
                               const float* __restrict__ bias,
                               float* __restrict__ C, int ldc,
                               int K, int act)
{
    __shared__ float As[16][68];
    __shared__ float Ws[16][68];

    const int bm = blockIdx.y * 64;
    const int bn = blockIdx.x * 64;
    const int tid = threadIdx.x;
    const int tx = tid & 15;
    const int ty = tid >> 4;
    const int lr = tid >> 2;         // 0..63: row within tile to load
    const int lk = (tid & 3) << 2;   // 0,4,8,12: k offset to load

    float acc[4][4];
#pragma unroll
    for (int i = 0; i < 4; i++)
#pragma unroll
        for (int j = 0; j < 4; j++) acc[i][j] = 0.f;

    const float* Ap = A + (size_t)(bm + lr) * lda + lk;
    const float* Wp = W + (size_t)(bn + lr) * ldw + lk;

    for (int k0 = 0; k0 < K; k0 += 16) {
        float4 av = *(const float4*)(Ap + k0);
        float4 wv = *(const float4*)(Wp + k0);
        __syncthreads();
        As[lk + 0][lr] = av.x; As[lk + 1][lr] = av.y;
        As[lk + 2][lr] = av.z; As[lk + 3][lr] = av.w;
        Ws[lk + 0][lr] = wv.x; Ws[lk + 1][lr] = wv.y;
        Ws[lk + 2][lr] = wv.z; Ws[lk + 3][lr] = wv.w;
        __syncthreads();
#pragma unroll
        for (int kk = 0; kk < 16; kk++) {
            float a0[4], b0[4];
            *(float4*)a0 = *(const float4*)&As[kk][ty << 2];
            *(float4*)b0 = *(const float4*)&Ws[kk][tx << 2];
#pragma unroll
            for (int i = 0; i < 4; i++)
#pragma unroll
                for (int j = 0; j < 4; j++)
                    acc[i][j] = fmaf(a0[i], b0[j], acc[i][j]);
        }
    }

#pragma unroll
    for (int i = 0; i < 4; i++) {
        int row = bm + (ty << 2) + i;
#pragma unroll
        for (int j = 0; j < 4; j++) {
            int col = bn + (tx << 2) + j;
            float v = acc[i][j] + bias[col];
            if (act) v = fmaxf(v, 0.f);
            C[(size_t)row * ldc + col] = v;
        }
    }
}

// ---------------------------------------------------------------------------
// GRU gate fusion: consumes gi/gh (biases already added by GEMM),
// updates hidden layer state in place (PyTorch r,z,n ordering).
// ---------------------------------------------------------------------------
__device__ __forceinline__ float sigmoidf_(float x) {
    return 1.f / (1.f + expf(-x));
}

__global__ void gru_gate_kernel(const float* __restrict__ gi,
                                const float* __restrict__ gh,
                                float* __restrict__ hstate)   // (B,H) layer slice
{
    const int idx = blockIdx.x * 256 + threadIdx.x;   // B_*H_ threads
    const int b = idx >> 10;
    const int j = idx & 1023;
    const float* gib = gi + (size_t)b * G3;
    const float* ghb = gh + (size_t)b * G3;
    float r = sigmoidf_(gib[j] + ghb[j]);
    float z = sigmoidf_(gib[H_ + j] + ghb[H_ + j]);
    float n = tanhf(fmaf(r, ghb[2 * H_ + j], gib[2 * H_ + j]));
    float h = hstate[idx];
    hstate[idx] = fmaf(z, h - n, n);   // (1-z)*n + z*h
}

// ---------------------------------------------------------------------------
// Launch
// ---------------------------------------------------------------------------
extern "C" void kernel_launch(void* const* d_in, const int* in_sizes, int n_in,
                              void* d_out, int out_size)
{
    const float* target  = (const float*)d_in[0];   // (B,T,D)
    const float* hidden0 = (const float*)d_in[1];   // (L,B,H)
    const float* enc     = (const float*)d_in[2];   // (B,S,H)
    const float* attn_W  = (const float*)d_in[3];   // (S, 2048)
    const float* attn_b  = (const float*)d_in[4];   // (S)
    const float* comb_W  = (const float*)d_in[5];   // (D, 2048)
    const float* comb_b  = (const float*)d_in[6];   // (D)
    const float* W_ih    = (const float*)d_in[7];   // (L, 3H, D)
    const float* W_hh    = (const float*)d_in[8];   // (L, 3H, H)
    const float* b_ih    = (const float*)d_in[9];   // (L, 3H)
    const float* b_hh    = (const float*)d_in[10];  // (L, 3H)
    const float* out1_W  = (const float*)d_in[11];  // (D, H)
    const float* out1_b  = (const float*)d_in[12];  // (D)
    const float* out2_W  = (const float*)d_in[13];  // (D, D)
    const float* out2_b  = (const float*)d_in[14];  // (D)

    float* outp = (float*)d_out;
    float* out_y  = outp + OUT_Y;    // (B,T,D)
    float* out_h  = outp + OUT_H;    // (L,B,H) — doubles as live hidden state
    float* out_aw = outp + OUT_AW;   // (B,T,S)

    float *cat2, *xc, *gi, *gh, *ybuf;
    cudaGetSymbolAddress((void**)&cat2, g_cat2);
    cudaGetSymbolAddress((void**)&xc,   g_xc);
    cudaGetSymbolAddress((void**)&gi,   g_gi);
    cudaGetSymbolAddress((void**)&gh,   g_gh);
    cudaGetSymbolAddress((void**)&ybuf, g_y);

    // Initialize live hidden state from input (in the output region)
    cudaMemcpyAsync(out_h, hidden0, (size_t)L_ * B_ * H_ * sizeof(float),
                    cudaMemcpyDeviceToDevice);

    float* h0 = out_h;                      // layer 0 state (B,H)
    float* h1 = out_h + (size_t)B_ * H_;    // layer 1 state (B,H)

    const dim3 gemm_blk(256);
    const dim3 grid_n1024(1024 / 64, B_ / 64);   // 16 x 4
    const dim3 grid_n3072(G3 / 64,  B_ / 64);    // 48 x 4

    for (int t = 0; t < T_; t++) {
        // 1) attention logits + softmax -> out_aw[:, t, :]
        attn_softmax_kernel<<<B_, 256>>>(target, out_h, attn_W, attn_b, out_aw, t);

        // 2) w_enc einsum fused with cat2 = [x, w_enc]
        wenc_cat_kernel<<<dim3(H_ / 256, B_), 256>>>(target, enc, out_aw, cat2, t);

        // 3) xc = relu(cat2 @ comb_W^T + comb_b)
        gemm_nt_kernel<<<grid_n1024, gemm_blk>>>(cat2, KCAT, comb_W, KCAT,
                                                 comb_b, xc, D_, KCAT, 1);

        // 4) GRU layer 0
        gemm_nt_kernel<<<grid_n3072, gemm_blk>>>(xc, D_, W_ih, D_,
                                                 b_ih, gi, G3, D_, 0);
        gemm_nt_kernel<<<grid_n3072, gemm_blk>>>(h0, H_, W_hh, H_,
                                                 b_hh, gh, G3, H_, 0);
        gru_gate_kernel<<<(B_ * H_) / 256, 256>>>(gi, gh, h0);

        // 5) GRU layer 1 (input = new h0)
        gemm_nt_kernel<<<grid_n3072, gemm_blk>>>(h0, H_, W_ih + (size_t)G3 * D_, D_,
                                                 b_ih + G3, gi, G3, H_, 0);
        gemm_nt_kernel<<<grid_n3072, gemm_blk>>>(h1, H_, W_hh + (size_t)G3 * H_, H_,
                                                 b_hh + G3, gh, G3, H_, 0);
        gru_gate_kernel<<<(B_ * H_) / 256, 256>>>(gi, gh, h1);

        // 6) output head: y = (h1 @ out1_W^T + b1) @ out2_W^T + b2 -> out_y[:, t, :]
        gemm_nt_kernel<<<grid_n1024, gemm_blk>>>(h1, H_, out1_W, H_,
                                                 out1_b, ybuf, D_, H_, 0);
        gemm_nt_kernel<<<grid_n1024, gemm_blk>>>(ybuf, D_, out2_W, D_,
                                                 out2_b, out_y + (size_t)t * D_,
                                                 T_ * D_, D_, 0);
    }
}

// round 4
// speedup vs baseline: 1.5886x; 1.5886x over previous
#include <cuda_runtime.h>
#include <math.h>

// Problem constants
#define B_   256
#define T_   36
#define S_   96
#define D_   1024
#define H_   1024
#define L_   2
#define KCAT 2048
#define G3   (3 * H_)
#define BT   (B_ * T_)

// Output buffer layout (flattened tuple: output, hidden_f, attn_weights)
#define OUT_Y   ((size_t)0)
#define OUT_H   ((size_t)B_ * T_ * D_)
#define OUT_AW  (OUT_H + (size_t)L_ * B_ * H_)

// Static scratch (no allocations allowed)
__device__ float g_wenc[B_ * H_];
__device__ float g_xc[B_ * D_];
__device__ float g_gi[B_ * G3];
__device__ float g_gh[B_ * G3];
__device__ float g_y[B_ * D_];
__device__ float g_pattn[BT * S_];     // precomputed x-part of attn logits (+bias)
__device__ float g_pcomb[BT * D_];     // precomputed x-part of combine (+bias)

struct GemmArgs {
    const float* A;
    const float* W;
    const float* bias;   // may be null
    const float* add;    // may be null (row-major (M,N), stride ldadd)
    int ldadd;
    float* C;
    int ldc;
};

// ---------------------------------------------------------------------------
// Templated fp32 GEMM: C = A(M,K) @ W(N,K)^T [+bias] [+add] [relu]
// 128 threads, tile TM x TN, per-thread RM x RN, K-chunk 16, double-buffered.
// SMEM rows padded by +4 floats so every row start stays 16B-aligned
// (LDS.128 alignment is a HW trap on sm_103a — +2 padding broke round 2).
// gridDim.z = 2 selects g1 (paired independent GEMM in one launch).
// ---------------------------------------------------------------------------
template<int TM, int TN, int RM, int RN>
__global__ void gemm_tpl(GemmArgs g0, GemmArgs g1, int lda, int ldw, int K, int act)
{
    constexpr int NT = (TM / RM) * (TN / RN);
    static_assert(NT == 128, "config must use 128 threads");
    constexpr int LA = TM / 32;   // float4 loads per thread for A chunk
    constexpr int LW = TN / 32;

    __shared__ float As[2][16][TM + 4];
    __shared__ float Ws[2][16][TN + 4];

    const GemmArgs g = blockIdx.z ? g1 : g0;
    const int bm = blockIdx.y * TM;
    const int bn = blockIdx.x * TN;
    const int tid = threadIdx.x;
    const int tn = tid % (TN / RN);
    const int tm = tid / (TN / RN);

    float acc[RM][RN];
#pragma unroll
    for (int i = 0; i < RM; i++)
#pragma unroll
        for (int j = 0; j < RN; j++) acc[i][j] = 0.f;

    const float* Abase = g.A + (size_t)bm * lda;
    const float* Wbase = g.W + (size_t)bn * ldw;

    float4 pa[LA], pw[LW];

    // prologue: load chunk 0
#pragma unroll
    for (int q = 0; q < LA; q++) {
        int idx = q * 128 + tid; int r = idx >> 2; int kq = (idx & 3) << 2;
        pa[q] = *(const float4*)(Abase + (size_t)r * lda + kq);
    }
#pragma unroll
    for (int q = 0; q < LW; q++) {
        int idx = q * 128 + tid; int r = idx >> 2; int kq = (idx & 3) << 2;
        pw[q] = *(const float4*)(Wbase + (size_t)r * ldw + kq);
    }
#pragma unroll
    for (int q = 0; q < LA; q++) {
        int idx = q * 128 + tid; int r = idx >> 2; int kq = (idx & 3) << 2;
        As[0][kq + 0][r] = pa[q].x; As[0][kq + 1][r] = pa[q].y;
        As[0][kq + 2][r] = pa[q].z; As[0][kq + 3][r] = pa[q].w;
    }
#pragma unroll
    for (int q = 0; q < LW; q++) {
        int idx = q * 128 + tid; int r = idx >> 2; int kq = (idx & 3) << 2;
        Ws[0][kq + 0][r] = pw[q].x; Ws[0][kq + 1][r] = pw[q].y;
        Ws[0][kq + 2][r] = pw[q].z; Ws[0][kq + 3][r] = pw[q].w;
    }
    __syncthreads();

    const int nb = K >> 4;
    for (int kb = 0; kb < nb; kb++) {
        const int buf = kb & 1;
        if (kb + 1 < nb) {
            const int k0 = (kb + 1) << 4;
#pragma unroll
            for (int q = 0; q < LA; q++) {
                int idx = q * 128 + tid; int r = idx >> 2; int kq = (idx & 3) << 2;
                pa[q] = *(const float4*)(Abase + (size_t)r * lda + k0 + kq);
            }
#pragma unroll
            for (int q = 0; q < LW; q++) {
                int idx = q * 128 + tid; int r = idx >> 2; int kq = (idx & 3) << 2;
                pw[q] = *(const float4*)(Wbase + (size_t)r * ldw + k0 + kq);
            }
        }
#pragma unroll
        for (int kk = 0; kk < 16; kk++) {
            float a[RM], b[RN];
#pragma unroll
            for (int i = 0; i < RM / 4; i++)
                *(float4*)(a + 4 * i) = *(const float4*)&As[buf][kk][tm * RM + 4 * i];
#pragma unroll
            for (int j = 0; j < RN / 4; j++)
                *(float4*)(b + 4 * j) = *(const float4*)&Ws[buf][kk][tn * RN + 4 * j];
#pragma unroll
            for (int i = 0; i < RM; i++)
#pragma unroll
                for (int j = 0; j < RN; j++)
                    acc[i][j] = fmaf(a[i], b[j], acc[i][j]);
        }
        if (kb + 1 < nb) {
            const int nxt = buf ^ 1;
#pragma unroll
            for (int q = 0; q < LA; q++) {
                int idx = q * 128 + tid; int r = idx >> 2; int kq = (idx & 3) << 2;
                As[nxt][kq + 0][r] = pa[q].x; As[nxt][kq + 1][r] = pa[q].y;
                As[nxt][kq + 2][r] = pa[q].z; As[nxt][kq + 3][r] = pa[q].w;
            }
#pragma unroll
            for (int q = 0; q < LW; q++) {
                int idx = q * 128 + tid; int r = idx >> 2; int kq = (idx & 3) << 2;
                Ws[nxt][kq + 0][r] = pw[q].x; Ws[nxt][kq + 1][r] = pw[q].y;
                Ws[nxt][kq + 2][r] = pw[q].z; Ws[nxt][kq + 3][r] = pw[q].w;
            }
            __syncthreads();
        }
    }

#pragma unroll
    for (int i = 0; i < RM; i++) {
        const int row = bm + tm * RM + i;
#pragma unroll
        for (int j = 0; j < RN; j++) {
            const int col = bn + tn * RN + j;
            float v = acc[i][j];
            if (g.bias) v += g.bias[col];
            if (g.add)  v += g.add[(size_t)row * g.ldadd + col];
            if (act)    v = fmaxf(v, 0.f);
            g.C[(size_t)row * g.ldc + col] = v;
        }
    }
}

// ---------------------------------------------------------------------------
// Per-step attention: logits = P_attn[:,t,:] + h @ attn_Wh^T, then softmax.
// ---------------------------------------------------------------------------
__global__ void attn_softmax_kernel(const float* __restrict__ pattn,
                                    const float* __restrict__ hstate,
                                    const float* __restrict__ Wh,  // attn_W+1024, stride KCAT
                                    float* __restrict__ aw_out,
                                    int t)
{
    const int b = blockIdx.x;
    const int tid = threadIdx.x;
    const int lane = tid & 31;
    const int w = tid >> 5;

    __shared__ float logits[S_];
    __shared__ float smax, ssum;

    const float* h = hstate + ((size_t)(L_ - 1) * B_ + b) * H_;

    for (int s = w; s < S_; s += 8) {
        const float* wr = Wh + (size_t)s * KCAT;
        float acc = 0.f;
#pragma unroll
        for (int c = 0; c < 8; c++) {
            int k = c * 128 + lane * 4;
            float4 hv = *(const float4*)(h + k);
            float4 wv = *(const float4*)(wr + k);
            acc = fmaf(hv.x, wv.x, acc); acc = fmaf(hv.y, wv.y, acc);
            acc = fmaf(hv.z, wv.z, acc); acc = fmaf(hv.w, wv.w, acc);
        }
#pragma unroll
        for (int o = 16; o > 0; o >>= 1)
            acc += __shfl_xor_sync(0xFFFFFFFFu, acc, o);
        if (lane == 0)
            logits[s] = acc + pattn[((size_t)b * T_ + t) * S_ + s];
    }
    __syncthreads();

    if (w == 0) {
        float m = -1e30f;
        for (int s = lane; s < S_; s += 32) m = fmaxf(m, logits[s]);
#pragma unroll
        for (int o = 16; o > 0; o >>= 1)
            m = fmaxf(m, __shfl_xor_sync(0xFFFFFFFFu, m, o));
        if (lane == 0) smax = m;
    }
    __syncthreads();
    if (tid < S_) logits[tid] = expf(logits[tid] - smax);
    __syncthreads();
    if (w == 0) {
        float s0 = 0.f;
        for (int s = lane; s < S_; s += 32) s0 += logits[s];
#pragma unroll
        for (int o = 16; o > 0; o >>= 1)
            s0 += __shfl_xor_sync(0xFFFFFFFFu, s0, o);
        if (lane == 0) ssum = s0;
    }
    __syncthreads();
    if (tid < S_)
        aw_out[((size_t)b * T_ + t) * S_ + tid] = logits[tid] / ssum;
}

// ---------------------------------------------------------------------------
// w_enc[b,h] = sum_s aw[b,t,s] * enc[b,s,h]
// ---------------------------------------------------------------------------
__global__ void wenc_kernel(const float* __restrict__ enc,
                            const float* __restrict__ aw,
                            float* __restrict__ wenc,
                            int t)
{
    const int b = blockIdx.y;
    const int h = blockIdx.x * 256 + threadIdx.x;

    __shared__ float a[S_];
    if (threadIdx.x < S_)
        a[threadIdx.x] = aw[((size_t)b * T_ + t) * S_ + threadIdx.x];
    __syncthreads();

    const float* e = enc + (size_t)b * S_ * H_ + h;
    float acc = 0.f;
#pragma unroll 8
    for (int s = 0; s < S_; s++)
        acc = fmaf(a[s], e[(size_t)s * H_], acc);

    wenc[(size_t)b * H_ + h] = acc;
}

// ---------------------------------------------------------------------------
// GRU gate fusion (PyTorch r,z,n ordering), updates h in place.
// ---------------------------------------------------------------------------
__device__ __forceinline__ float sigmoidf_(float x) { return 1.f / (1.f + expf(-x)); }

__global__ void gru_gate_kernel(const float* __restrict__ gi,
                                const float* __restrict__ gh,
                                float* __restrict__ hstate)
{
    const int idx = blockIdx.x * 256 + threadIdx.x;
    const int b = idx >> 10;
    const int j = idx & 1023;
    const float* gib = gi + (size_t)b * G3;
    const float* ghb = gh + (size_t)b * G3;
    float r = sigmoidf_(gib[j] + ghb[j]);
    float z = sigmoidf_(gib[H_ + j] + ghb[H_ + j]);
    float n = tanhf(fmaf(r, ghb[2 * H_ + j], gib[2 * H_ + j]));
    float h = hstate[idx];
    hstate[idx] = fmaf(z, h - n, n);
}

// ---------------------------------------------------------------------------
// Launch
// ---------------------------------------------------------------------------
extern "C" void kernel_launch(void* const* d_in, const int* in_sizes, int n_in,
                              void* d_out, int out_size)
{
    const float* target  = (const float*)d_in[0];
    const float* hidden0 = (const float*)d_in[1];
    const float* enc     = (const float*)d_in[2];
    const float* attn_W  = (const float*)d_in[3];
    const float* attn_b  = (const float*)d_in[4];
    const float* comb_W  = (const float*)d_in[5];
    const float* comb_b  = (const float*)d_in[6];
    const float* W_ih    = (const float*)d_in[7];
    const float* W_hh    = (const float*)d_in[8];
    const float* b_ih    = (const float*)d_in[9];
    const float* b_hh    = (const float*)d_in[10];
    const float* out1_W  = (const float*)d_in[11];
    const float* out1_b  = (const float*)d_in[12];
    const float* out2_W  = (const float*)d_in[13];
    const float* out2_b  = (const float*)d_in[14];

    float* outp = (float*)d_out;
    float* out_y  = outp + OUT_Y;
    float* out_h  = outp + OUT_H;
    float* out_aw = outp + OUT_AW;

    float *wenc, *xc, *gi, *gh, *ybuf, *pattn, *pcomb;
    cudaGetSymbolAddress((void**)&wenc,  g_wenc);
    cudaGetSymbolAddress((void**)&xc,    g_xc);
    cudaGetSymbolAddress((void**)&gi,    g_gi);
    cudaGetSymbolAddress((void**)&gh,    g_gh);
    cudaGetSymbolAddress((void**)&ybuf,  g_y);
    cudaGetSymbolAddress((void**)&pattn, g_pattn);
    cudaGetSymbolAddress((void**)&pcomb, g_pcomb);

    cudaMemcpyAsync(out_h, hidden0, (size_t)L_ * B_ * H_ * sizeof(float),
                    cudaMemcpyDeviceToDevice);

    float* h0 = out_h;
    float* h1 = out_h + (size_t)B_ * H_;

    // ---- Precompute target-dependent halves for all steps (well-filled GEMMs)
    {   // P_attn = target_flat @ attn_W[:, :1024]^T + attn_b   (BT x 96)
        GemmArgs a{target, attn_W, attn_b, nullptr, 0, pattn, S_};
        gemm_tpl<64, 32, 4, 4><<<dim3(S_ / 32, BT / 64, 1), 128>>>(a, a, D_, KCAT, 1024, 0);
    }
    {   // P_comb = target_flat @ comb_W[:, :1024]^T + comb_b   (BT x 1024)
        GemmArgs a{target, comb_W, comb_b, nullptr, 0, pcomb, D_};
        gemm_tpl<64, 64, 8, 4><<<dim3(D_ / 64, BT / 64, 1), 128>>>(a, a, D_, KCAT, 1024, 0);
    }

    for (int t = 0; t < T_; t++) {
        // 1) attention (h-part K=1024 + precomputed) + softmax
        attn_softmax_kernel<<<B_, 256>>>(pattn, out_h, attn_W + 1024, out_aw, t);

        // 2) w_enc einsum
        wenc_kernel<<<dim3(H_ / 256, B_), 256>>>(enc, out_aw, wenc, t);

        // 3) xc = relu(wenc @ comb_W[:,1024:]^T + P_comb[:,t,:])
        {
            GemmArgs a{wenc, comb_W + 1024, nullptr, pcomb + (size_t)t * D_, T_ * D_, xc, D_};
            gemm_tpl<32, 64, 4, 4><<<dim3(D_ / 64, B_ / 32, 1), 128>>>(a, a, H_, KCAT, 1024, 1);
        }

        // 4) GRU layer 0: gi and gh in ONE launch (gridDim.z = 2)
        {
            GemmArgs a{xc, W_ih, b_ih, nullptr, 0, gi, G3};
            GemmArgs b{h0, W_hh, b_hh, nullptr, 0, gh, G3};
            gemm_tpl<64, 64, 8, 4><<<dim3(G3 / 64, B_ / 64, 2), 128>>>(a, b, D_, D_, 1024, 0);
        }
        gru_gate_kernel<<<(B_ * H_) / 256, 256>>>(gi, gh, h0);

        // 5) GRU layer 1
        {
            GemmArgs a{h0, W_ih + (size_t)G3 * D_, b_ih + G3, nullptr, 0, gi, G3};
            GemmArgs b{h1, W_hh + (size_t)G3 * H_, b_hh + G3, nullptr, 0, gh, G3};
            gemm_tpl<64, 64, 8, 4><<<dim3(G3 / 64, B_ / 64, 2), 128>>>(a, b, H_, H_, 1024, 0);
        }
        gru_gate_kernel<<<(B_ * H_) / 256, 256>>>(gi, gh, h1);

        // 6) output head
        {
            GemmArgs a{h1, out1_W, out1_b, nullptr, 0, ybuf, D_};
            gemm_tpl<32, 64, 4, 4><<<dim3(D_ / 64, B_ / 32, 1), 128>>>(a, a, H_, H_, 1024, 0);
        }
        {
            GemmArgs a{ybuf, out2_W, out2_b, nullptr, 0, out_y + (size_t)t * D_, T_ * D_};
            gemm_tpl<32, 64, 4, 4><<<dim3(D_ / 64, B_ / 32, 1), 128>>>(a, a, D_, D_, 1024, 0);
        }
    }
}

// round 7
// speedup vs baseline: 2.7366x; 1.7227x over previous
#include <cuda_runtime.h>
#include <cuda_bf16.h>
#include <math.h>
#include <stdint.h>

// Problem constants
#define B_   256
#define T_   36
#define S_   96
#define D_   1024
#define H_   1024
#define L_   2
#define KCAT 2048
#define G3   (3 * H_)
#define BT   (B_ * T_)

// Output buffer layout (flattened tuple: output, hidden_f, attn_weights)
#define OUT_Y   ((size_t)0)
#define OUT_H   ((size_t)B_ * T_ * D_)
#define OUT_AW  (OUT_H + (size_t)L_ * B_ * H_)

typedef __nv_bfloat16 bf16;

// ---------------- static scratch (no allocations allowed) ------------------
__device__ float g_pattn[BT * S_];
__device__ float g_pcomb[BT * D_];
__device__ float g_gi[B_ * G3];
__device__ float g_gh[B_ * G3];

// bf16 hi/lo splits
__device__ bf16 g_tgt_hi[BT * D_],   g_tgt_lo[BT * D_];
__device__ bf16 g_combx_hi[D_ * D_], g_combx_lo[D_ * D_];   // comb_W[:, :1024]
__device__ bf16 g_combh_hi[D_ * D_], g_combh_lo[D_ * D_];   // comb_W[:, 1024:]
__device__ bf16 g_wih_hi[L_ * G3 * D_], g_wih_lo[L_ * G3 * D_];
__device__ bf16 g_whh_hi[L_ * G3 * H_], g_whh_lo[L_ * G3 * H_];
__device__ bf16 g_o1_hi[D_ * H_],  g_o1_lo[D_ * H_];
__device__ bf16 g_o2_hi[D_ * D_],  g_o2_lo[D_ * D_];
__device__ bf16 g_xc_hi[B_ * D_],  g_xc_lo[B_ * D_];
__device__ bf16 g_h0_hi[B_ * H_],  g_h0_lo[B_ * H_];
__device__ bf16 g_h1_hi[B_ * H_],  g_h1_lo[B_ * H_];
__device__ bf16 g_we_hi[B_ * H_],  g_we_lo[B_ * H_];
__device__ bf16 g_hseq_hi[BT * H_], g_hseq_lo[BT * H_];
__device__ bf16 g_y_hi[BT * D_],   g_y_lo[BT * D_];

// ---------------------------------------------------------------------------
// bf16 split helper
// ---------------------------------------------------------------------------
__device__ __forceinline__ void split1(float x, bf16& h, bf16& l) {
    h = __float2bfloat16(x);
    l = __float2bfloat16(x - __bfloat162float(h));
}

__global__ void split_kernel(const float* __restrict__ src, int srcld, int srcoff,
                             int cols, bf16* __restrict__ hi, bf16* __restrict__ lo,
                             int n)
{
    int i = blockIdx.x * 256 + threadIdx.x;
    if (i >= n) return;
    int r = i / cols, c = i - r * cols;
    float x = src[(size_t)r * srcld + srcoff + c];
    bf16 h, l; split1(x, h, l);
    hi[i] = h; lo[i] = l;
}

// ---------------------------------------------------------------------------
// Tensor-core GEMM with bf16 hi/lo 3-term split, fp32 accumulate.
// C(M,N) = A(M,K) @ W(N,K)^T [+bias] [+add] [relu]; optional bf16-split output.
// CTA 64x64, 4 warps (warp tile 32x32), K-chunk 16, double buffered.
// ---------------------------------------------------------------------------
struct MMAArgs {
    const bf16 *Ahi, *Alo, *Whi, *Wlo;
    const float* bias;   // may be null
    const float* add;    // may be null
    int ldadd;
    float* C;            // may be null
    int ldc;
    bf16 *Chi, *Clo;     // may be null (packed, stride ldc)
};

__device__ __forceinline__ void ldsm4(uint32_t* r, uint32_t addr) {
    asm volatile("ldmatrix.sync.aligned.m8n8.x4.shared.b16 {%0,%1,%2,%3}, [%4];\n"
                 : "=r"(r[0]), "=r"(r[1]), "=r"(r[2]), "=r"(r[3]) : "r"(addr));
}

#define MMA16816(c, a, b) \
    asm volatile("mma.sync.aligned.m16n8k16.row.col.f32.bf16.bf16.f32 " \
                 "{%0,%1,%2,%3}, {%4,%5,%6,%7}, {%8,%9}, {%0,%1,%2,%3};\n" \
                 : "+f"((c)[0]), "+f"((c)[1]), "+f"((c)[2]), "+f"((c)[3]) \
                 : "r"((a)[0]), "r"((a)[1]), "r"((a)[2]), "r"((a)[3]), \
                   "r"((b)[0]), "r"((b)[1]))

#define SK 24   // smem row stride in bf16 (16 data + 8 pad; 48B, 16B-aligned)

__global__ __launch_bounds__(128) void mma_gemm(MMAArgs g0, MMAArgs g1, int K, int act)
{
    const MMAArgs g = blockIdx.z ? g1 : g0;

    __shared__ bf16 sm[2 * 4 * 64 * SK];   // [buf][Ahi,Alo,Whi,Wlo][64][SK]

    const int tid = threadIdx.x;
    const int lane = tid & 31;
    const int wid = tid >> 5;
    const int bm = blockIdx.y * 64;
    const int bn = blockIdx.x * 64;
    const int wm = (wid >> 1) * 32;
    const int wn = (wid & 1) * 32;

    // GMEM load mapping: each thread 1 int4 (8 bf16) per array per chunk
    const int lr = tid >> 1;
    const int lc = (tid & 1) * 8;

    const bf16* src0 = g.Ahi + (size_t)(bm + lr) * K + lc;
    const bf16* src1 = g.Alo + (size_t)(bm + lr) * K + lc;
    const bf16* src2 = g.Whi + (size_t)(bn + lr) * K + lc;
    const bf16* src3 = g.Wlo + (size_t)(bn + lr) * K + lc;

    const uint32_t s0 = (uint32_t)__cvta_generic_to_shared(sm);
    const int sidx = lr * SK + lc;

    // ldmatrix offsets (bytes, within one 64xSK array)
    uint32_t aoff0 = ((wm +  0 + (lane & 15)) * SK + ((lane >> 4) << 3)) * 2;
    uint32_t aoff1 = ((wm + 16 + (lane & 15)) * SK + ((lane >> 4) << 3)) * 2;
    uint32_t boff0 = ((wn +  0 + (lane & 7) + ((lane >> 4) << 3)) * SK +
                      (((lane >> 3) & 1) << 3)) * 2;
    uint32_t boff1 = ((wn + 16 + (lane & 7) + ((lane >> 4) << 3)) * SK +
                      (((lane >> 3) & 1) << 3)) * 2;

    float acc[2][4][4];
#pragma unroll
    for (int i = 0; i < 2; i++)
#pragma unroll
        for (int j = 0; j < 4; j++)
#pragma unroll
            for (int q = 0; q < 4; q++) acc[i][j][q] = 0.f;

    int4 rg0, rg1, rg2, rg3;

    // prologue
    rg0 = *(const int4*)(src0); rg1 = *(const int4*)(src1);
    rg2 = *(const int4*)(src2); rg3 = *(const int4*)(src3);
    *(int4*)&sm[(0 * 4 + 0) * 64 * SK + sidx] = rg0;
    *(int4*)&sm[(0 * 4 + 1) * 64 * SK + sidx] = rg1;
    *(int4*)&sm[(0 * 4 + 2) * 64 * SK + sidx] = rg2;
    *(int4*)&sm[(0 * 4 + 3) * 64 * SK + sidx] = rg3;
    __syncthreads();

    const int nkc = K >> 4;
    for (int kc = 0; kc < nkc; kc++) {
        const int buf = kc & 1;
        if (kc + 1 < nkc) {
            const size_t o = (size_t)(kc + 1) << 4;
            rg0 = *(const int4*)(src0 + o); rg1 = *(const int4*)(src1 + o);
            rg2 = *(const int4*)(src2 + o); rg3 = *(const int4*)(src3 + o);
        }

        const uint32_t bb = s0 + (uint32_t)(buf * 4 * 64 * SK * 2);
        uint32_t A[2][2][4];   // [hl][mt]
        uint32_t Bv[2][8];     // [hl][ntile pairs]
        ldsm4(A[0][0], bb + 0 * (64 * SK * 2) + aoff0);
        ldsm4(A[0][1], bb + 0 * (64 * SK * 2) + aoff1);
        ldsm4(A[1][0], bb + 1 * (64 * SK * 2) + aoff0);
        ldsm4(A[1][1], bb + 1 * (64 * SK * 2) + aoff1);
        ldsm4(&Bv[0][0], bb + 2 * (64 * SK * 2) + boff0);
        ldsm4(&Bv[0][4], bb + 2 * (64 * SK * 2) + boff1);
        ldsm4(&Bv[1][0], bb + 3 * (64 * SK * 2) + boff0);
        ldsm4(&Bv[1][4], bb + 3 * (64 * SK * 2) + boff1);

#pragma unroll
        for (int mt = 0; mt < 2; mt++) {
#pragma unroll
            for (int nt = 0; nt < 4; nt++) {
                uint32_t* bh = &Bv[0][(nt >> 1) * 4 + (nt & 1) * 2];
                uint32_t* bl = &Bv[1][(nt >> 1) * 4 + (nt & 1) * 2];
                MMA16816(acc[mt][nt], A[0][mt], bh);  // hi*hi
                MMA16816(acc[mt][nt], A[0][mt], bl);  // hi*lo
                MMA16816(acc[mt][nt], A[1][mt], bh);  // lo*hi
            }
        }

        if (kc + 1 < nkc) {
            const int nxt = buf ^ 1;
            *(int4*)&sm[(nxt * 4 + 0) * 64 * SK + sidx] = rg0;
            *(int4*)&sm[(nxt * 4 + 1) * 64 * SK + sidx] = rg1;
            *(int4*)&sm[(nxt * 4 + 2) * 64 * SK + sidx] = rg2;
            *(int4*)&sm[(nxt * 4 + 3) * 64 * SK + sidx] = rg3;
            __syncthreads();
        }
    }

    // epilogue
#pragma unroll
    for (int mt = 0; mt < 2; mt++) {
#pragma unroll
        for (int nt = 0; nt < 4; nt++) {
            const int col = bn + wn + nt * 8 + ((lane & 3) << 1);
            float b0 = 0.f, b1 = 0.f;
            if (g.bias) { b0 = g.bias[col]; b1 = g.bias[col + 1]; }
#pragma unroll
            for (int half = 0; half < 2; half++) {
                const int row = bm + wm + mt * 16 + (lane >> 2) + half * 8;
                float v0 = acc[mt][nt][half * 2 + 0] + b0;
                float v1 = acc[mt][nt][half * 2 + 1] + b1;
                if (g.add) {
                    v0 += g.add[(size_t)row * g.ldadd + col];
                    v1 += g.add[(size_t)row * g.ldadd + col + 1];
                }
                if (act) { v0 = fmaxf(v0, 0.f); v1 = fmaxf(v1, 0.f); }
                if (g.C) {
                    float2 o; o.x = v0; o.y = v1;
                    *(float2*)&g.C[(size_t)row * g.ldc + col] = o;
                }
                if (g.Chi) {
                    bf16 h0, l0, h1, l1;
                    split1(v0, h0, l0); split1(v1, h1, l1);
                    __nv_bfloat162 ph; ph.x = h0; ph.y = h1;
                    __nv_bfloat162 pl; pl.x = l0; pl.y = l1;
                    *(__nv_bfloat162*)&g.Chi[(size_t)row * g.ldc + col] = ph;
                    *(__nv_bfloat162*)&g.Clo[(size_t)row * g.ldc + col] = pl;
                }
            }
        }
    }
}

// ---------------------------------------------------------------------------
// fp32 GEMM (kept for P_attn, N=96 which isn't a multiple of 64)
// ---------------------------------------------------------------------------
struct GemmArgs {
    const float* A; const float* W; const float* bias;
    const float* add; int ldadd; float* C; int ldc;
};

template<int TM, int TN, int RM, int RN>
__global__ void gemm_tpl(GemmArgs g0, GemmArgs g1, int lda, int ldw, int K, int act)
{
    constexpr int LA = TM / 32;
    constexpr int LW = TN / 32;

    __shared__ float As[2][16][TM + 4];
    __shared__ float Ws[2][16][TN + 4];

    const GemmArgs g = blockIdx.z ? g1 : g0;
    const int bm = blockIdx.y * TM;
    const int bn = blockIdx.x * TN;
    const int tid = threadIdx.x;
    const int tn = tid % (TN / RN);
    const int tm = tid / (TN / RN);

    float acc[RM][RN];
#pragma unroll
    for (int i = 0; i < RM; i++)
#pragma unroll
        for (int j = 0; j < RN; j++) acc[i][j] = 0.f;

    const float* Abase = g.A + (size_t)bm * lda;
    const float* Wbase = g.W + (size_t)bn * ldw;
    float4 pa[LA], pw[LW];

#pragma unroll
    for (int q = 0; q < LA; q++) {
        int idx = q * 128 + tid; int r = idx >> 2; int kq = (idx & 3) << 2;
        pa[q] = *(const float4*)(Abase + (size_t)r * lda + kq);
    }
#pragma unroll
    for (int q = 0; q < LW; q++) {
        int idx = q * 128 + tid; int r = idx >> 2; int kq = (idx & 3) << 2;
        pw[q] = *(const float4*)(Wbase + (size_t)r * ldw + kq);
    }
#pragma unroll
    for (int q = 0; q < LA; q++) {
        int idx = q * 128 + tid; int r = idx >> 2; int kq = (idx & 3) << 2;
        As[0][kq + 0][r] = pa[q].x; As[0][kq + 1][r] = pa[q].y;
        As[0][kq + 2][r] = pa[q].z; As[0][kq + 3][r] = pa[q].w;
    }
#pragma unroll
    for (int q = 0; q < LW; q++) {
        int idx = q * 128 + tid; int r = idx >> 2; int kq = (idx & 3) << 2;
        Ws[0][kq + 0][r] = pw[q].x; Ws[0][kq + 1][r] = pw[q].y;
        Ws[0][kq + 2][r] = pw[q].z; Ws[0][kq + 3][r] = pw[q].w;
    }
    __syncthreads();

    const int nb = K >> 4;
    for (int kb = 0; kb < nb; kb++) {
        const int buf = kb & 1;
        if (kb + 1 < nb) {
            const int k0 = (kb + 1) << 4;
#pragma unroll
            for (int q = 0; q < LA; q++) {
                int idx = q * 128 + tid; int r = idx >> 2; int kq = (idx & 3) << 2;
                pa[q] = *(const float4*)(Abase + (size_t)r * lda + k0 + kq);
            }
#pragma unroll
            for (int q = 0; q < LW; q++) {
                int idx = q * 128 + tid; int r = idx >> 2; int kq = (idx & 3) << 2;
                pw[q] = *(const float4*)(Wbase + (size_t)r * ldw + k0 + kq);
            }
        }
#pragma unroll
        for (int kk = 0; kk < 16; kk++) {
            float a[RM], b[RN];
#pragma unroll
            for (int i = 0; i < RM / 4; i++)
                *(float4*)(a + 4 * i) = *(const float4*)&As[buf][kk][tm * RM + 4 * i];
#pragma unroll
            for (int j = 0; j < RN / 4; j++)
                *(float4*)(b + 4 * j) = *(const float4*)&Ws[buf][kk][tn * RN + 4 * j];
#pragma unroll
            for (int i = 0; i < RM; i++)
#pragma unroll
                for (int j = 0; j < RN; j++)
                    acc[i][j] = fmaf(a[i], b[j], acc[i][j]);
        }
        if (kb + 1 < nb) {
            const int nxt = buf ^ 1;
#pragma unroll
            for (int q = 0; q < LA; q++) {
                int idx = q * 128 + tid; int r = idx >> 2; int kq = (idx & 3) << 2;
                As[nxt][kq + 0][r] = pa[q].x; As[nxt][kq + 1][r] = pa[q].y;
                As[nxt][kq + 2][r] = pa[q].z; As[nxt][kq + 3][r] = pa[q].w;
            }
#pragma unroll
            for (int q = 0; q < LW; q++) {
                int idx = q * 128 + tid; int r = idx >> 2; int kq = (idx & 3) << 2;
                Ws[nxt][kq + 0][r] = pw[q].x; Ws[nxt][kq + 1][r] = pw[q].y;
                Ws[nxt][kq + 2][r] = pw[q].z; Ws[nxt][kq + 3][r] = pw[q].w;
            }
            __syncthreads();
        }
    }

#pragma unroll
    for (int i = 0; i < RM; i++) {
        const int row = bm + tm * RM + i;
#pragma unroll
        for (int j = 0; j < RN; j++) {
            const int col = bn + tn * RN + j;
            float v = acc[i][j];
            if (g.bias) v += g.bias[col];
            if (g.add)  v += g.add[(size_t)row * g.ldadd + col];
            if (act)    v = fmaxf(v, 0.f);
            g.C[(size_t)row * g.ldc + col] = v;
        }
    }
}

// ---------------------------------------------------------------------------
// Attention: logits = P_attn[:,t,:] + h1 @ attn_Wh^T, softmax.
// ---------------------------------------------------------------------------
__global__ void attn_softmax_kernel(const float* __restrict__ pattn,
                                    const float* __restrict__ hstate,
                                    const float* __restrict__ Wh,
                                    float* __restrict__ aw_out,
                                    int t)
{
    const int b = blockIdx.x;
    const int tid = threadIdx.x;
    const int lane = tid & 31;
    const int w = tid >> 5;

    __shared__ float logits[S_];
    __shared__ float smax, ssum;

    const float* h = hstate + ((size_t)(L_ - 1) * B_ + b) * H_;

    for (int s = w; s < S_; s += 8) {
        const float* wr = Wh + (size_t)s * KCAT;
        float acc = 0.f;
#pragma unroll
        for (int c = 0; c < 8; c++) {
            int k = c * 128 + lane * 4;
            float4 hv = *(const float4*)(h + k);
            float4 wv = *(const float4*)(wr + k);
            acc = fmaf(hv.x, wv.x, acc); acc = fmaf(hv.y, wv.y, acc);
            acc = fmaf(hv.z, wv.z, acc); acc = fmaf(hv.w, wv.w, acc);
        }
#pragma unroll
        for (int o = 16; o > 0; o >>= 1)
            acc += __shfl_xor_sync(0xFFFFFFFFu, acc, o);
        if (lane == 0)
            logits[s] = acc + pattn[((size_t)b * T_ + t) * S_ + s];
    }
    __syncthreads();

    if (w == 0) {
        float m = -1e30f;
        for (int s = lane; s < S_; s += 32) m = fmaxf(m, logits[s]);
#pragma unroll
        for (int o = 16; o > 0; o >>= 1)
            m = fmaxf(m, __shfl_xor_sync(0xFFFFFFFFu, m, o));
        if (lane == 0) smax = m;
    }
    __syncthreads();
    if (tid < S_) logits[tid] = expf(logits[tid] - smax);
    __syncthreads();
    if (w == 0) {
        float s0 = 0.f;
        for (int s = lane; s < S_; s += 32) s0 += logits[s];
#pragma unroll
        for (int o = 16; o > 0; o >>= 1)
            s0 += __shfl_xor_sync(0xFFFFFFFFu, s0, o);
        if (lane == 0) ssum = s0;
    }
    __syncthreads();
    if (tid < S_)
        aw_out[((size_t)b * T_ + t) * S_ + tid] = logits[tid] / ssum;
}

// ---------------------------------------------------------------------------
// w_enc[b,h] = sum_s aw[b,t,s] * enc[b,s,h]; writes bf16 hi/lo splits.
// ---------------------------------------------------------------------------
__global__ void wenc_kernel(const float* __restrict__ enc,
                            const float* __restrict__ aw,
                            bf16* __restrict__ whi, bf16* __restrict__ wlo,
                            int t)
{
    const int b = blockIdx.y;
    const int h = blockIdx.x * 256 + threadIdx.x;

    __shared__ float a[S_];
    if (threadIdx.x < S_)
        a[threadIdx.x] = aw[((size_t)b * T_ + t) * S_ + threadIdx.x];
    __syncthreads();

    const float* e = enc + (size_t)b * S_ * H_ + h;
    float acc = 0.f;
#pragma unroll 8
    for (int s = 0; s < S_; s++)
        acc = fmaf(a[s], e[(size_t)s * H_], acc);

    bf16 hi, lo; split1(acc, hi, lo);
    whi[(size_t)b * H_ + h] = hi;
    wlo[(size_t)b * H_ + h] = lo;
}

// ---------------------------------------------------------------------------
// GRU gate fusion; writes fp32 h (in-place) + bf16 splits + optional seq log.
// ---------------------------------------------------------------------------
__device__ __forceinline__ float sigmoidf_(float x) { return 1.f / (1.f + expf(-x)); }

__global__ void gru_gate_kernel(const float* __restrict__ gi,
                                const float* __restrict__ gh,
                                float* __restrict__ hstate,
                                bf16* __restrict__ hhi, bf16* __restrict__ hlo,
                                bf16* __restrict__ shi, bf16* __restrict__ slo,
                                int t)
{
    const int idx = blockIdx.x * 256 + threadIdx.x;
    const int b = idx >> 10;
    const int j = idx & 1023;
    const float* gib = gi + (size_t)b * G3;
    const float* ghb = gh + (size_t)b * G3;
    float r = sigmoidf_(gib[j] + ghb[j]);
    float z = sigmoidf_(gib[H_ + j] + ghb[H_ + j]);
    float n = tanhf(fmaf(r, ghb[2 * H_ + j], gib[2 * H_ + j]));
    float h = hstate[idx];
    float hn = fmaf(z, h - n, n);
    hstate[idx] = hn;
    bf16 hi, lo; split1(hn, hi, lo);
    hhi[idx] = hi; hlo[idx] = lo;
    if (shi) {
        size_t o = ((size_t)b * T_ + t) * H_ + j;
        shi[o] = hi; slo[o] = lo;
    }
}

// ---------------------------------------------------------------------------
// Launch
// ---------------------------------------------------------------------------
static inline void* sym(const void* s) { void* p; cudaGetSymbolAddress(&p, s); return p; }

extern "C" void kernel_launch(void* const* d_in, const int* in_sizes, int n_in,
                              void* d_out, int out_size)
{
    const float* target  = (const float*)d_in[0];
    const float* hidden0 = (const float*)d_in[1];
    const float* enc     = (const float*)d_in[2];
    const float* attn_W  = (const float*)d_in[3];
    const float* attn_b  = (const float*)d_in[4];
    const float* comb_W  = (const float*)d_in[5];
    const float* comb_b  = (const float*)d_in[6];
    const float* W_ih    = (const float*)d_in[7];
    const float* W_hh    = (const float*)d_in[8];
    const float* b_ih    = (const float*)d_in[9];
    const float* b_hh    = (const float*)d_in[10];
    const float* out1_W  = (const float*)d_in[11];
    const float* out1_b  = (const float*)d_in[12];
    const float* out2_W  = (const float*)d_in[13];
    const float* out2_b  = (const float*)d_in[14];

    float* outp = (float*)d_out;
    float* out_y  = outp + OUT_Y;
    float* out_h  = outp + OUT_H;
    float* out_aw = outp + OUT_AW;

    float* pattn = (float*)sym(g_pattn);
    float* pcomb = (float*)sym(g_pcomb);
    float* gi    = (float*)sym(g_gi);
    float* gh    = (float*)sym(g_gh);

    bf16 *tgt_hi = (bf16*)sym(g_tgt_hi), *tgt_lo = (bf16*)sym(g_tgt_lo);
    bf16 *cx_hi = (bf16*)sym(g_combx_hi), *cx_lo = (bf16*)sym(g_combx_lo);
    bf16 *ch_hi = (bf16*)sym(g_combh_hi), *ch_lo = (bf16*)sym(g_combh_lo);
    bf16 *wih_hi = (bf16*)sym(g_wih_hi), *wih_lo = (bf16*)sym(g_wih_lo);
    bf16 *whh_hi = (bf16*)sym(g_whh_hi), *whh_lo = (bf16*)sym(g_whh_lo);
    bf16 *o1_hi = (bf16*)sym(g_o1_hi), *o1_lo = (bf16*)sym(g_o1_lo);
    bf16 *o2_hi = (bf16*)sym(g_o2_hi), *o2_lo = (bf16*)sym(g_o2_lo);
    bf16 *xc_hi = (bf16*)sym(g_xc_hi), *xc_lo = (bf16*)sym(g_xc_lo);
    bf16 *h0_hi = (bf16*)sym(g_h0_hi), *h0_lo = (bf16*)sym(g_h0_lo);
    bf16 *h1_hi = (bf16*)sym(g_h1_hi), *h1_lo = (bf16*)sym(g_h1_lo);
    bf16 *we_hi = (bf16*)sym(g_we_hi), *we_lo = (bf16*)sym(g_we_lo);
    bf16 *hs_hi = (bf16*)sym(g_hseq_hi), *hs_lo = (bf16*)sym(g_hseq_lo);
    bf16 *y_hi = (bf16*)sym(g_y_hi), *y_lo = (bf16*)sym(g_y_lo);

    cudaMemcpyAsync(out_h, hidden0, (size_t)L_ * B_ * H_ * sizeof(float),
                    cudaMemcpyDeviceToDevice);

    float* h0 = out_h;
    float* h1 = out_h + (size_t)B_ * H_;

    // ---- startup: bf16 splits of weights / target / initial hidden
    const int SB = 256;
    {
        int n;
        n = BT * D_;       split_kernel<<<(n + SB - 1) / SB, SB>>>(target, D_, 0, D_, tgt_hi, tgt_lo, n);
        n = D_ * D_;       split_kernel<<<(n + SB - 1) / SB, SB>>>(comb_W, KCAT, 0, D_, cx_hi, cx_lo, n);
        n = D_ * D_;       split_kernel<<<(n + SB - 1) / SB, SB>>>(comb_W, KCAT, D_, D_, ch_hi, ch_lo, n);
        n = L_ * G3 * D_;  split_kernel<<<(n + SB - 1) / SB, SB>>>(W_ih, D_, 0, D_, wih_hi, wih_lo, n);
        n = L_ * G3 * H_;  split_kernel<<<(n + SB - 1) / SB, SB>>>(W_hh, H_, 0, H_, whh_hi, whh_lo, n);
        n = D_ * H_;       split_kernel<<<(n + SB - 1) / SB, SB>>>(out1_W, H_, 0, H_, o1_hi, o1_lo, n);
        n = D_ * D_;       split_kernel<<<(n + SB - 1) / SB, SB>>>(out2_W, D_, 0, D_, o2_hi, o2_lo, n);
        n = B_ * H_;       split_kernel<<<(n + SB - 1) / SB, SB>>>(h0, H_, 0, H_, h0_hi, h0_lo, n);
        n = B_ * H_;       split_kernel<<<(n + SB - 1) / SB, SB>>>(h1, H_, 0, H_, h1_hi, h1_lo, n);
    }

    // ---- precompute target-dependent halves
    {   // P_comb = target @ comb_W[:, :1024]^T + comb_b   (mma, BT x 1024)
        MMAArgs a{tgt_hi, tgt_lo, cx_hi, cx_lo, comb_b, nullptr, 0,
                  pcomb, D_, nullptr, nullptr};
        mma_gemm<<<dim3(D_ / 64, BT / 64, 1), 128>>>(a, a, D_, 0);
    }
    {   // P_attn = target @ attn_W[:, :1024]^T + attn_b   (fp32, N=96)
        GemmArgs a{target, attn_W, attn_b, nullptr, 0, pattn, S_};
        gemm_tpl<64, 32, 4, 4><<<dim3(S_ / 32, BT / 64, 1), 128>>>(a, a, D_, KCAT, 1024, 0);
    }

    for (int t = 0; t < T_; t++) {
        // 1) attention + softmax
        attn_softmax_kernel<<<B_, 256>>>(pattn, out_h, attn_W + 1024, out_aw, t);

        // 2) w_enc (writes bf16 splits)
        wenc_kernel<<<dim3(H_ / 256, B_), 256>>>(enc, out_aw, we_hi, we_lo, t);

        // 3) xc = relu(wenc @ comb_W[:,1024:]^T + P_comb[:,t,:]) -> splits only
        {
            MMAArgs a{we_hi, we_lo, ch_hi, ch_lo, nullptr,
                      pcomb + (size_t)t * D_, T_ * D_,
                      nullptr, D_, xc_hi, xc_lo};
            mma_gemm<<<dim3(D_ / 64, B_ / 64, 1), 128>>>(a, a, D_, 1);
        }

        // 4) GRU layer 0 (gi/gh paired via gridDim.z)
        {
            MMAArgs a{xc_hi, xc_lo, wih_hi, wih_lo, b_ih, nullptr, 0,
                      gi, G3, nullptr, nullptr};
            MMAArgs b{h0_hi, h0_lo, whh_hi, whh_lo, b_hh, nullptr, 0,
                      gh, G3, nullptr, nullptr};
            mma_gemm<<<dim3(G3 / 64, B_ / 64, 2), 128>>>(a, b, D_, 0);
        }
        gru_gate_kernel<<<(B_ * H_) / 256, 256>>>(gi, gh, h0, h0_hi, h0_lo,
                                                  nullptr, nullptr, t);

        // 5) GRU layer 1
        {
            MMAArgs a{h0_hi, h0_lo, wih_hi + (size_t)G3 * D_, wih_lo + (size_t)G3 * D_,
                      b_ih + G3, nullptr, 0, gi, G3, nullptr, nullptr};
            MMAArgs b{h1_hi, h1_lo, whh_hi + (size_t)G3 * H_, whh_lo + (size_t)G3 * H_,
                      b_hh + G3, nullptr, 0, gh, G3, nullptr, nullptr};
            mma_gemm<<<dim3(G3 / 64, B_ / 64, 2), 128>>>(a, b, H_, 0);
        }
        gru_gate_kernel<<<(B_ * H_) / 256, 256>>>(gi, gh, h1, h1_hi, h1_lo,
                                                  hs_hi, hs_lo, t);
    }

    // ---- output head, batched over all 36 steps (two big GEMMs)
    {   // y = hseq @ out1_W^T + out1_b -> bf16 splits
        MMAArgs a{hs_hi, hs_lo, o1_hi, o1_lo, out1_b, nullptr, 0,
                  nullptr, D_, y_hi, y_lo};
        mma_gemm<<<dim3(D_ / 64, BT / 64, 1), 128>>>(a, a, H_, 0);
    }
    {   // out_y = y @ out2_W^T + out2_b
        MMAArgs a{y_hi, y_lo, o2_hi, o2_lo, out2_b, nullptr, 0,
                  out_y, D_, nullptr, nullptr};
        mma_gemm<<<dim3(D_ / 64, BT / 64, 1), 128>>>(a, a, D_, 0);
    }
}

// round 10
// speedup vs baseline: 3.1230x; 1.1412x over previous
#include <cuda_runtime.h>
#include <cuda_bf16.h>
#include <math.h>
#include <stdint.h>

// Problem constants
#define B_   256
#define T_   36
#define S_   96
#define D_   1024
#define H_   1024
#define L_   2
#define KCAT 2048
#define G3   (3 * H_)
#define BT   (B_ * T_)

// Output buffer layout (flattened tuple: output, hidden_f, attn_weights)
#define OUT_Y   ((size_t)0)
#define OUT_H   ((size_t)B_ * T_ * D_)
#define OUT_AW  (OUT_H + (size_t)L_ * B_ * H_)

typedef __nv_bfloat16 bf16;

// ---------------- static scratch (no allocations allowed) ------------------
__device__ float g_pattn[BT * S_];
__device__ float g_pcomb[BT * D_];
__device__ float g_gi[B_ * G3];
__device__ float g_gh[B_ * G3];

// bf16 hi/lo splits
__device__ bf16 g_tgt_hi[BT * D_],   g_tgt_lo[BT * D_];
__device__ bf16 g_combx_hi[D_ * D_], g_combx_lo[D_ * D_];
__device__ bf16 g_combh_hi[D_ * D_], g_combh_lo[D_ * D_];
__device__ bf16 g_wih_hi[L_ * G3 * D_], g_wih_lo[L_ * G3 * D_];
__device__ bf16 g_whh_hi[L_ * G3 * H_], g_whh_lo[L_ * G3 * H_];
__device__ bf16 g_o1_hi[D_ * H_],  g_o1_lo[D_ * H_];
__device__ bf16 g_o2_hi[D_ * D_],  g_o2_lo[D_ * D_];
__device__ bf16 g_xc_hi[B_ * D_],  g_xc_lo[B_ * D_];
__device__ bf16 g_h0_hi[B_ * H_],  g_h0_lo[B_ * H_];
__device__ bf16 g_h1_hi[B_ * H_],  g_h1_lo[B_ * H_];
__device__ bf16 g_we_hi[B_ * H_],  g_we_lo[B_ * H_];
__device__ bf16 g_hseq_hi[BT * H_], g_hseq_lo[BT * H_];
__device__ bf16 g_y_hi[BT * D_],   g_y_lo[BT * D_];

// ---------------------------------------------------------------------------
__device__ __forceinline__ void split1(float x, bf16& h, bf16& l) {
    h = __float2bfloat16(x);
    l = __float2bfloat16(x - __bfloat162float(h));
}

__global__ void split_kernel(const float* __restrict__ src, int srcld, int srcoff,
                             int cols, bf16* __restrict__ hi, bf16* __restrict__ lo,
                             int n)
{
    int i = blockIdx.x * 256 + threadIdx.x;
    if (i >= n) return;
    int r = i / cols, c = i - r * cols;
    float x = src[(size_t)r * srcld + srcoff + c];
    bf16 h, l; split1(x, h, l);
    hi[i] = h; lo[i] = l;
}

// ---------------------------------------------------------------------------
// Tensor-core GEMM v2: bf16 hi/lo 3-term split, fp32 accumulate.
// CTA 128x64, 256 threads (8 warps, warp tile 32x32), K-chunk 32,
// 2-stage cp.async pipeline, dynamic SMEM (61,440 B).
// ---------------------------------------------------------------------------
struct MMAArgs {
    const bf16 *Ahi, *Alo, *Whi, *Wlo;
    const float* bias;   // may be null
    const float* add;    // may be null
    int ldadd;
    float* C;            // may be null
    int ldc;
    bf16 *Chi, *Clo;     // may be null (packed, stride ldc)
};

__device__ __forceinline__ void ldsm4(uint32_t* r, uint32_t addr) {
    asm volatile("ldmatrix.sync.aligned.m8n8.x4.shared.b16 {%0,%1,%2,%3}, [%4];\n"
                 : "=r"(r[0]), "=r"(r[1]), "=r"(r[2]), "=r"(r[3]) : "r"(addr));
}

#define MMA16816(c, a, b) \
    asm volatile("mma.sync.aligned.m16n8k16.row.col.f32.bf16.bf16.f32 " \
                 "{%0,%1,%2,%3}, {%4,%5,%6,%7}, {%8,%9}, {%0,%1,%2,%3};\n" \
                 : "+f"((c)[0]), "+f"((c)[1]), "+f"((c)[2]), "+f"((c)[3]) \
                 : "r"((a)[0]), "r"((a)[1]), "r"((a)[2]), "r"((a)[3]), \
                   "r"((b)[0]), "r"((b)[1]))

#define CPA16(saddr, gptr) \
    asm volatile("cp.async.cg.shared.global [%0], [%1], 16;\n" \
                 :: "r"(saddr), "l"(gptr))
#define CP_COMMIT() asm volatile("cp.async.commit_group;\n")
#define CP_WAIT1()  asm volatile("cp.async.wait_group 1;\n")
#define CP_WAIT0()  asm volatile("cp.async.wait_group 0;\n")

// SMEM element layout per stage (stride 40 bf16 = 80 B rows; 16B aligned;
// bank walk 20*r mod 32 covers all banks -> LDSM conflict-free):
//   Ahi [0,5120)  Alo [5120,10240)  Whi [10240,12800)  Wlo [12800,15360)
#define SKE      40
#define STAGE_E  15360
#define STAGE_B  30720
#define SMEM2_B  (2 * STAGE_B)

__global__ __launch_bounds__(256) void mma_gemm2(MMAArgs g0, MMAArgs g1, int K, int act)
{
    extern __shared__ bf16 smd[];
    const MMAArgs g = blockIdx.z ? g1 : g0;

    const int tid = threadIdx.x;
    const int lane = tid & 31;
    const int wid = tid >> 5;
    const int bm = blockIdx.y * 128;
    const int bn = blockIdx.x * 64;
    const int wm = (wid & 3) * 32;
    const int wn = (wid >> 2) * 32;

    const uint32_t s0 = (uint32_t)__cvta_generic_to_shared(smd);

    // GMEM row/col for cp.async: A arrays use 2 int4/thread, W arrays 1
    const int ar0 = (0 * 256 + tid) >> 2, ac0 = (((0 * 256 + tid) & 3) << 3);
    const int ar1 = (1 * 256 + tid) >> 2, ac1 = (((1 * 256 + tid) & 3) << 3);
    const int wr = tid >> 2,              wc = ((tid & 3) << 3);

    const bf16* Ahi = g.Ahi + (size_t)bm * K;
    const bf16* Alo = g.Alo + (size_t)bm * K;
    const bf16* Whi = g.Whi + (size_t)bn * K;
    const bf16* Wlo = g.Wlo + (size_t)bn * K;

#define LOAD_STAGE(st, ko) do {                                               \
        const uint32_t sb_ = s0 + (uint32_t)(st) * STAGE_B;                   \
        CPA16(sb_ + (uint32_t)((ar0 * SKE + ac0) * 2),                        \
              Ahi + (size_t)ar0 * K + (ko) + ac0);                            \
        CPA16(sb_ + (uint32_t)((ar1 * SKE + ac1) * 2),                        \
              Ahi + (size_t)ar1 * K + (ko) + ac1);                            \
        CPA16(sb_ + (uint32_t)((5120 + ar0 * SKE + ac0) * 2),                 \
              Alo + (size_t)ar0 * K + (ko) + ac0);                            \
        CPA16(sb_ + (uint32_t)((5120 + ar1 * SKE + ac1) * 2),                 \
              Alo + (size_t)ar1 * K + (ko) + ac1);                            \
        CPA16(sb_ + (uint32_t)((10240 + wr * SKE + wc) * 2),                  \
              Whi + (size_t)wr * K + (ko) + wc);                              \
        CPA16(sb_ + (uint32_t)((12800 + wr * SKE + wc) * 2),                  \
              Wlo + (size_t)wr * K + (ko) + wc);                              \
        CP_COMMIT();                                                          \
    } while (0)

    // LDSM lane offsets (bytes, within one array)
    const uint32_t aoffb0 = ((wm +  0 + (lane & 15)) * SKE + ((lane >> 4) << 3)) * 2;
    const uint32_t aoffb1 = ((wm + 16 + (lane & 15)) * SKE + ((lane >> 4) << 3)) * 2;
    const uint32_t boffb0 = ((wn +  0 + (lane & 7) + ((lane >> 4) << 3)) * SKE +
                             (((lane >> 3) & 1) << 3)) * 2;
    const uint32_t boffb1 = ((wn + 16 + (lane & 7) + ((lane >> 4) << 3)) * SKE +
                             (((lane >> 3) & 1) << 3)) * 2;

    float acc[2][4][4];
#pragma unroll
    for (int i = 0; i < 2; i++)
#pragma unroll
        for (int j = 0; j < 4; j++)
#pragma unroll
            for (int q = 0; q < 4; q++) acc[i][j][q] = 0.f;

    const int nkc = K >> 5;
    LOAD_STAGE(0, 0);
    if (nkc > 1) { LOAD_STAGE(1, 32); CP_WAIT1(); } else { CP_WAIT0(); }
    __syncthreads();

    for (int kc = 0; kc < nkc; kc++) {
        const int st = kc & 1;
        const uint32_t sb = s0 + (uint32_t)st * STAGE_B;
        const uint32_t sAhi = sb, sAlo = sb + 10240;
        const uint32_t sWhi = sb + 20480, sWlo = sb + 25600;

#pragma unroll
        for (int ks = 0; ks < 2; ks++) {
            const uint32_t kso = ks * 32;   // 16 elems * 2B
            uint32_t Ah[2][4], Al[2][4], Bh[2][4], Bl[2][4];
            ldsm4(Ah[0], sAhi + aoffb0 + kso);
            ldsm4(Ah[1], sAhi + aoffb1 + kso);
            ldsm4(Al[0], sAlo + aoffb0 + kso);
            ldsm4(Al[1], sAlo + aoffb1 + kso);
            ldsm4(Bh[0], sWhi + boffb0 + kso);
            ldsm4(Bh[1], sWhi + boffb1 + kso);
            ldsm4(Bl[0], sWlo + boffb0 + kso);
            ldsm4(Bl[1], sWlo + boffb1 + kso);

#pragma unroll
            for (int mt = 0; mt < 2; mt++) {
#pragma unroll
                for (int nt = 0; nt < 4; nt++) {
                    uint32_t* bh = &Bh[nt >> 1][(nt & 1) * 2];
                    uint32_t* bl = &Bl[nt >> 1][(nt & 1) * 2];
                    MMA16816(acc[mt][nt], Ah[mt], bh);
                    MMA16816(acc[mt][nt], Ah[mt], bl);
                    MMA16816(acc[mt][nt], Al[mt], bh);
                }
            }
        }

        __syncthreads();
        if (kc + 2 < nkc) { LOAD_STAGE(st, (kc + 2) << 5); CP_WAIT1(); }
        else              { CP_WAIT0(); }
        __syncthreads();
    }

    // epilogue
#pragma unroll
    for (int mt = 0; mt < 2; mt++) {
#pragma unroll
        for (int nt = 0; nt < 4; nt++) {
            const int col = bn + wn + nt * 8 + ((lane & 3) << 1);
            float b0 = 0.f, b1 = 0.f;
            if (g.bias) { b0 = g.bias[col]; b1 = g.bias[col + 1]; }
#pragma unroll
            for (int half = 0; half < 2; half++) {
                const int row = bm + wm + mt * 16 + (lane >> 2) + half * 8;
                float v0 = acc[mt][nt][half * 2 + 0] + b0;
                float v1 = acc[mt][nt][half * 2 + 1] + b1;
                if (g.add) {
                    v0 += g.add[(size_t)row * g.ldadd + col];
                    v1 += g.add[(size_t)row * g.ldadd + col + 1];
                }
                if (act) { v0 = fmaxf(v0, 0.f); v1 = fmaxf(v1, 0.f); }
                if (g.C) {
                    float2 o; o.x = v0; o.y = v1;
                    *(float2*)&g.C[(size_t)row * g.ldc + col] = o;
                }
                if (g.Chi) {
                    bf16 h0, l0, h1, l1;
                    split1(v0, h0, l0); split1(v1, h1, l1);
                    __nv_bfloat162 ph; ph.x = h0; ph.y = h1;
                    __nv_bfloat162 pl; pl.x = l0; pl.y = l1;
                    *(__nv_bfloat162*)&g.Chi[(size_t)row * g.ldc + col] = ph;
                    *(__nv_bfloat162*)&g.Clo[(size_t)row * g.ldc + col] = pl;
                }
            }
        }
    }
}

// ---------------------------------------------------------------------------
// fp32 GEMM (kept for P_attn, N=96)
// ---------------------------------------------------------------------------
struct GemmArgs {
    const float* A; const float* W; const float* bias;
    const float* add; int ldadd; float* C; int ldc;
};

template<int TM, int TN, int RM, int RN>
__global__ void gemm_tpl(GemmArgs g0, GemmArgs g1, int lda, int ldw, int K, int act)
{
    constexpr int LA = TM / 32;
    constexpr int LW = TN / 32;

    __shared__ float As[2][16][TM + 4];
    __shared__ float Ws[2][16][TN + 4];

    const GemmArgs g = blockIdx.z ? g1 : g0;
    const int bm = blockIdx.y * TM;
    const int bn = blockIdx.x * TN;
    const int tid = threadIdx.x;
    const int tn = tid % (TN / RN);
    const int tm = tid / (TN / RN);

    float acc[RM][RN];
#pragma unroll
    for (int i = 0; i < RM; i++)
#pragma unroll
        for (int j = 0; j < RN; j++) acc[i][j] = 0.f;

    const float* Abase = g.A + (size_t)bm * lda;
    const float* Wbase = g.W + (size_t)bn * ldw;
    float4 pa[LA], pw[LW];

#pragma unroll
    for (int q = 0; q < LA; q++) {
        int idx = q * 128 + tid; int r = idx >> 2; int kq = (idx & 3) << 2;
        pa[q] = *(const float4*)(Abase + (size_t)r * lda + kq);
    }
#pragma unroll
    for (int q = 0; q < LW; q++) {
        int idx = q * 128 + tid; int r = idx >> 2; int kq = (idx & 3) << 2;
        pw[q] = *(const float4*)(Wbase + (size_t)r * ldw + kq);
    }
#pragma unroll
    for (int q = 0; q < LA; q++) {
        int idx = q * 128 + tid; int r = idx >> 2; int kq = (idx & 3) << 2;
        As[0][kq + 0][r] = pa[q].x; As[0][kq + 1][r] = pa[q].y;
        As[0][kq + 2][r] = pa[q].z; As[0][kq + 3][r] = pa[q].w;
    }
#pragma unroll
    for (int q = 0; q < LW; q++) {
        int idx = q * 128 + tid; int r = idx >> 2; int kq = (idx & 3) << 2;
        Ws[0][kq + 0][r] = pw[q].x; Ws[0][kq + 1][r] = pw[q].y;
        Ws[0][kq + 2][r] = pw[q].z; Ws[0][kq + 3][r] = pw[q].w;
    }
    __syncthreads();

    const int nb = K >> 4;
    for (int kb = 0; kb < nb; kb++) {
        const int buf = kb & 1;
        if (kb + 1 < nb) {
            const int k0 = (kb + 1) << 4;
#pragma unroll
            for (int q = 0; q < LA; q++) {
                int idx = q * 128 + tid; int r = idx >> 2; int kq = (idx & 3) << 2;
                pa[q] = *(const float4*)(Abase + (size_t)r * lda + k0 + kq);
            }
#pragma unroll
            for (int q = 0; q < LW; q++) {
                int idx = q * 128 + tid; int r = idx >> 2; int kq = (idx & 3) << 2;
                pw[q] = *(const float4*)(Wbase + (size_t)r * ldw + k0 + kq);
            }
        }
#pragma unroll
        for (int kk = 0; kk < 16; kk++) {
            float a[RM], b[RN];
#pragma unroll
            for (int i = 0; i < RM / 4; i++)
                *(float4*)(a + 4 * i) = *(const float4*)&As[buf][kk][tm * RM + 4 * i];
#pragma unroll
            for (int j = 0; j < RN / 4; j++)
                *(float4*)(b + 4 * j) = *(const float4*)&Ws[buf][kk][tn * RN + 4 * j];
#pragma unroll
            for (int i = 0; i < RM; i++)
#pragma unroll
                for (int j = 0; j < RN; j++)
                    acc[i][j] = fmaf(a[i], b[j], acc[i][j]);
        }
        if (kb + 1 < nb) {
            const int nxt = buf ^ 1;
#pragma unroll
            for (int q = 0; q < LA; q++) {
                int idx = q * 128 + tid; int r = idx >> 2; int kq = (idx & 3) << 2;
                As[nxt][kq + 0][r] = pa[q].x; As[nxt][kq + 1][r] = pa[q].y;
                As[nxt][kq + 2][r] = pa[q].z; As[nxt][kq + 3][r] = pa[q].w;
            }
#pragma unroll
            for (int q = 0; q < LW; q++) {
                int idx = q * 128 + tid; int r = idx >> 2; int kq = (idx & 3) << 2;
                Ws[nxt][kq + 0][r] = pw[q].x; Ws[nxt][kq + 1][r] = pw[q].y;
                Ws[nxt][kq + 2][r] = pw[q].z; Ws[nxt][kq + 3][r] = pw[q].w;
            }
            __syncthreads();
        }
    }

#pragma unroll
    for (int i = 0; i < RM; i++) {
        const int row = bm + tm * RM + i;
#pragma unroll
        for (int j = 0; j < RN; j++) {
            const int col = bn + tn * RN + j;
            float v = acc[i][j];
            if (g.bias) v += g.bias[col];
            if (g.add)  v += g.add[(size_t)row * g.ldadd + col];
            if (act)    v = fmaxf(v, 0.f);
            g.C[(size_t)row * g.ldc + col] = v;
        }
    }
}

// ---------------------------------------------------------------------------
// Attention: logits = P_attn[:,t,:] + h1 @ attn_Wh^T, softmax.
// ---------------------------------------------------------------------------
__global__ void attn_softmax_kernel(const float* __restrict__ pattn,
                                    const float* __restrict__ hstate,
                                    const float* __restrict__ Wh,
                                    float* __restrict__ aw_out,
                                    int t)
{
    const int b = blockIdx.x;
    const int tid = threadIdx.x;
    const int lane = tid & 31;
    const int w = tid >> 5;

    __shared__ float logits[S_];
    __shared__ float smax, ssum;

    const float* h = hstate + ((size_t)(L_ - 1) * B_ + b) * H_;

    for (int s = w; s < S_; s += 8) {
        const float* wr = Wh + (size_t)s * KCAT;
        float acc = 0.f;
#pragma unroll
        for (int c = 0; c < 8; c++) {
            int k = c * 128 + lane * 4;
            float4 hv = *(const float4*)(h + k);
            float4 wv = *(const float4*)(wr + k);
            acc = fmaf(hv.x, wv.x, acc); acc = fmaf(hv.y, wv.y, acc);
            acc = fmaf(hv.z, wv.z, acc); acc = fmaf(hv.w, wv.w, acc);
        }
#pragma unroll
        for (int o = 16; o > 0; o >>= 1)
            acc += __shfl_xor_sync(0xFFFFFFFFu, acc, o);
        if (lane == 0)
            logits[s] = acc + pattn[((size_t)b * T_ + t) * S_ + s];
    }
    __syncthreads();

    if (w == 0) {
        float m = -1e30f;
        for (int s = lane; s < S_; s += 32) m = fmaxf(m, logits[s]);
#pragma unroll
        for (int o = 16; o > 0; o >>= 1)
            m = fmaxf(m, __shfl_xor_sync(0xFFFFFFFFu, m, o));
        if (lane == 0) smax = m;
    }
    __syncthreads();
    if (tid < S_) logits[tid] = expf(logits[tid] - smax);
    __syncthreads();
    if (w == 0) {
        float s0 = 0.f;
        for (int s = lane; s < S_; s += 32) s0 += logits[s];
#pragma unroll
        for (int o = 16; o > 0; o >>= 1)
            s0 += __shfl_xor_sync(0xFFFFFFFFu, s0, o);
        if (lane == 0) ssum = s0;
    }
    __syncthreads();
    if (tid < S_)
        aw_out[((size_t)b * T_ + t) * S_ + tid] = logits[tid] / ssum;
}

// ---------------------------------------------------------------------------
// w_enc[b,h] = sum_s aw[b,t,s] * enc[b,s,h]; writes bf16 hi/lo splits.
// ---------------------------------------------------------------------------
__global__ void wenc_kernel(const float* __restrict__ enc,
                            const float* __restrict__ aw,
                            bf16* __restrict__ whi, bf16* __restrict__ wlo,
                            int t)
{
    const int b = blockIdx.y;
    const int h = blockIdx.x * 256 + threadIdx.x;

    __shared__ float a[S_];
    if (threadIdx.x < S_)
        a[threadIdx.x] = aw[((size_t)b * T_ + t) * S_ + threadIdx.x];
    __syncthreads();

    const float* e = enc + (size_t)b * S_ * H_ + h;
    float acc = 0.f;
#pragma unroll 8
    for (int s = 0; s < S_; s++)
        acc = fmaf(a[s], e[(size_t)s * H_], acc);

    bf16 hi, lo; split1(acc, hi, lo);
    whi[(size_t)b * H_ + h] = hi;
    wlo[(size_t)b * H_ + h] = lo;
}

// ---------------------------------------------------------------------------
// GRU gate fusion
// ---------------------------------------------------------------------------
__device__ __forceinline__ float sigmoidf_(float x) { return 1.f / (1.f + expf(-x)); }

__global__ void gru_gate_kernel(const float* __restrict__ gi,
                                const float* __restrict__ gh,
                                float* __restrict__ hstate,
                                bf16* __restrict__ hhi, bf16* __restrict__ hlo,
                                bf16* __restrict__ shi, bf16* __restrict__ slo,
                                int t)
{
    const int idx = blockIdx.x * 256 + threadIdx.x;
    const int b = idx >> 10;
    const int j = idx & 1023;
    const float* gib = gi + (size_t)b * G3;
    const float* ghb = gh + (size_t)b * G3;
    float r = sigmoidf_(gib[j] + ghb[j]);
    float z = sigmoidf_(gib[H_ + j] + ghb[H_ + j]);
    float n = tanhf(fmaf(r, ghb[2 * H_ + j], gib[2 * H_ + j]));
    float h = hstate[idx];
    float hn = fmaf(z, h - n, n);
    hstate[idx] = hn;
    bf16 hi, lo; split1(hn, hi, lo);
    hhi[idx] = hi; hlo[idx] = lo;
    if (shi) {
        size_t o = ((size_t)b * T_ + t) * H_ + j;
        shi[o] = hi; slo[o] = lo;
    }
}

// ---------------------------------------------------------------------------
// Launch
// ---------------------------------------------------------------------------
static inline void* sym(const void* s) { void* p; cudaGetSymbolAddress(&p, s); return p; }

extern "C" void kernel_launch(void* const* d_in, const int* in_sizes, int n_in,
                              void* d_out, int out_size)
{
    const float* target  = (const float*)d_in[0];
    const float* hidden0 = (const float*)d_in[1];
    const float* enc     = (const float*)d_in[2];
    const float* attn_W  = (const float*)d_in[3];
    const float* attn_b  = (const float*)d_in[4];
    const float* comb_W  = (const float*)d_in[5];
    const float* comb_b  = (const float*)d_in[6];
    const float* W_ih    = (const float*)d_in[7];
    const float* W_hh    = (const float*)d_in[8];
    const float* b_ih    = (const float*)d_in[9];
    const float* b_hh    = (const float*)d_in[10];
    const float* out1_W  = (const float*)d_in[11];
    const float* out1_b  = (const float*)d_in[12];
    const float* out2_W  = (const float*)d_in[13];
    const float* out2_b  = (const float*)d_in[14];

    float* outp = (float*)d_out;
    float* out_y  = outp + OUT_Y;
    float* out_h  = outp + OUT_H;
    float* out_aw = outp + OUT_AW;

    float* pattn = (float*)sym(g_pattn);
    float* pcomb = (float*)sym(g_pcomb);
    float* gi    = (float*)sym(g_gi);
    float* gh    = (float*)sym(g_gh);

    bf16 *tgt_hi = (bf16*)sym(g_tgt_hi), *tgt_lo = (bf16*)sym(g_tgt_lo);
    bf16 *cx_hi = (bf16*)sym(g_combx_hi), *cx_lo = (bf16*)sym(g_combx_lo);
    bf16 *ch_hi = (bf16*)sym(g_combh_hi), *ch_lo = (bf16*)sym(g_combh_lo);
    bf16 *wih_hi = (bf16*)sym(g_wih_hi), *wih_lo = (bf16*)sym(g_wih_lo);
    bf16 *whh_hi = (bf16*)sym(g_whh_hi), *whh_lo = (bf16*)sym(g_whh_lo);
    bf16 *o1_hi = (bf16*)sym(g_o1_hi), *o1_lo = (bf16*)sym(g_o1_lo);
    bf16 *o2_hi = (bf16*)sym(g_o2_hi), *o2_lo = (bf16*)sym(g_o2_lo);
    bf16 *xc_hi = (bf16*)sym(g_xc_hi), *xc_lo = (bf16*)sym(g_xc_lo);
    bf16 *h0_hi = (bf16*)sym(g_h0_hi), *h0_lo = (bf16*)sym(g_h0_lo);
    bf16 *h1_hi = (bf16*)sym(g_h1_hi), *h1_lo = (bf16*)sym(g_h1_lo);
    bf16 *we_hi = (bf16*)sym(g_we_hi), *we_lo = (bf16*)sym(g_we_lo);
    bf16 *hs_hi = (bf16*)sym(g_hseq_hi), *hs_lo = (bf16*)sym(g_hseq_lo);
    bf16 *y_hi = (bf16*)sym(g_y_hi), *y_lo = (bf16*)sym(g_y_lo);

    // Allow 61,440 B dynamic smem on mma_gemm2 (attribute set, not an alloc)
    static int attr_done = 0;
    if (!attr_done) {
        cudaFuncSetAttribute(mma_gemm2,
                             cudaFuncAttributeMaxDynamicSharedMemorySize, SMEM2_B);
        attr_done = 1;
    }

    cudaMemcpyAsync(out_h, hidden0, (size_t)L_ * B_ * H_ * sizeof(float),
                    cudaMemcpyDeviceToDevice);

    float* h0 = out_h;
    float* h1 = out_h + (size_t)B_ * H_;

    // ---- startup: bf16 splits
    const int SB = 256;
    {
        int n;
        n = BT * D_;       split_kernel<<<(n + SB - 1) / SB, SB>>>(target, D_, 0, D_, tgt_hi, tgt_lo, n);
        n = D_ * D_;       split_kernel<<<(n + SB - 1) / SB, SB>>>(comb_W, KCAT, 0, D_, cx_hi, cx_lo, n);
        n = D_ * D_;       split_kernel<<<(n + SB - 1) / SB, SB>>>(comb_W, KCAT, D_, D_, ch_hi, ch_lo, n);
        n = L_ * G3 * D_;  split_kernel<<<(n + SB - 1) / SB, SB>>>(W_ih, D_, 0, D_, wih_hi, wih_lo, n);
        n = L_ * G3 * H_;  split_kernel<<<(n + SB - 1) / SB, SB>>>(W_hh, H_, 0, H_, whh_hi, whh_lo, n);
        n = D_ * H_;       split_kernel<<<(n + SB - 1) / SB, SB>>>(out1_W, H_, 0, H_, o1_hi, o1_lo, n);
        n = D_ * D_;       split_kernel<<<(n + SB - 1) / SB, SB>>>(out2_W, D_, 0, D_, o2_hi, o2_lo, n);
        n = B_ * H_;       split_kernel<<<(n + SB - 1) / SB, SB>>>(h0, H_, 0, H_, h0_hi, h0_lo, n);
        n = B_ * H_;       split_kernel<<<(n + SB - 1) / SB, SB>>>(h1, H_, 0, H_, h1_hi, h1_lo, n);
    }

    // ---- precompute target-dependent halves
    {   // P_comb = target @ comb_W[:, :1024]^T + comb_b
        MMAArgs a{tgt_hi, tgt_lo, cx_hi, cx_lo, comb_b, nullptr, 0,
                  pcomb, D_, nullptr, nullptr};
        mma_gemm2<<<dim3(D_ / 64, BT / 128, 1), 256, SMEM2_B>>>(a, a, D_, 0);
    }
    {   // P_attn = target @ attn_W[:, :1024]^T + attn_b   (fp32, N=96)
        GemmArgs a{target, attn_W, attn_b, nullptr, 0, pattn, S_};
        gemm_tpl<64, 32, 4, 4><<<dim3(S_ / 32, BT / 64, 1), 128>>>(a, a, D_, KCAT, 1024, 0);
    }

    for (int t = 0; t < T_; t++) {
        // 1) attention + softmax
        attn_softmax_kernel<<<B_, 256>>>(pattn, out_h, attn_W + 1024, out_aw, t);

        // 2) w_enc (writes bf16 splits)
        wenc_kernel<<<dim3(H_ / 256, B_), 256>>>(enc, out_aw, we_hi, we_lo, t);

        // 3) xc = relu(wenc @ comb_W[:,1024:]^T + P_comb[:,t,:]) -> splits
        {
            MMAArgs a{we_hi, we_lo, ch_hi, ch_lo, nullptr,
                      pcomb + (size_t)t * D_, T_ * D_,
                      nullptr, D_, xc_hi, xc_lo};
            mma_gemm2<<<dim3(D_ / 64, B_ / 128, 1), 256, SMEM2_B>>>(a, a, D_, 1);
        }

        // 4) GRU layer 0 (gi/gh paired via gridDim.z)
        {
            MMAArgs a{xc_hi, xc_lo, wih_hi, wih_lo, b_ih, nullptr, 0,
                      gi, G3, nullptr, nullptr};
            MMAArgs b{h0_hi, h0_lo, whh_hi, whh_lo, b_hh, nullptr, 0,
                      gh, G3, nullptr, nullptr};
            mma_gemm2<<<dim3(G3 / 64, B_ / 128, 2), 256, SMEM2_B>>>(a, b, D_, 0);
        }
        gru_gate_kernel<<<(B_ * H_) / 256, 256>>>(gi, gh, h0, h0_hi, h0_lo,
                                                  nullptr, nullptr, t);

        // 5) GRU layer 1
        {
            MMAArgs a{h0_hi, h0_lo, wih_hi + (size_t)G3 * D_, wih_lo + (size_t)G3 * D_,
                      b_ih + G3, nullptr, 0, gi, G3, nullptr, nullptr};
            MMAArgs b{h1_hi, h1_lo, whh_hi + (size_t)G3 * H_, whh_lo + (size_t)G3 * H_,
                      b_hh + G3, nullptr, 0, gh, G3, nullptr, nullptr};
            mma_gemm2<<<dim3(G3 / 64, B_ / 128, 2), 256, SMEM2_B>>>(a, b, H_, 0);
        }
        gru_gate_kernel<<<(B_ * H_) / 256, 256>>>(gi, gh, h1, h1_hi, h1_lo,
                                                  hs_hi, hs_lo, t);
    }

    // ---- output head, batched over all 36 steps
    {   // y = hseq @ out1_W^T + out1_b -> bf16 splits
        MMAArgs a{hs_hi, hs_lo, o1_hi, o1_lo, out1_b, nullptr, 0,
                  nullptr, D_, y_hi, y_lo};
        mma_gemm2<<<dim3(D_ / 64, BT / 128, 1), 256, SMEM2_B>>>(a, a, H_, 0);
    }
    {   // out_y = y @ out2_W^T + out2_b
        MMAArgs a{y_hi, y_lo, o2_hi, o2_lo, out2_b, nullptr, 0,
                  out_y, D_, nullptr, nullptr};
        mma_gemm2<<<dim3(D_ / 64, BT / 128, 1), 256, SMEM2_B>>>(a, a, D_, 0);
    }
}